// round 11
// baseline (speedup 1.0000x reference)
#include <cuda_runtime.h>
#include <cuda_fp16.h>
#include <math.h>
#include <stdint.h>

// Problem constants
#define NN    20000
#define NPAD  20096      // 157 * 128, padded M for GEMM tiles
#define EE    320000
#define IN_CH 256
#define TYPE_DIM 64
#define F_IN  320
#define R     8
#define HEADS 8
#define HOUT  512

// ---------------- scratch (device globals) --------------------------------
__device__ __half   g_h16[(size_t)NPAD * F_IN];         // fp16 hi part
__device__ __half   g_h16lo[(size_t)NPAD * F_IN];       // fp16 residual
__device__ uint32_t g_w16p[(size_t)R * (F_IN / 2) * HOUT];  // W packed k-pairs half2
__device__ float    g_wqk[(size_t)R * 16 * F_IN];       // fused q/k weights
__device__ uint32_t g_wqk16h[(F_IN / 2) * 128];
__device__ uint32_t g_wqk16l[(F_IN / 2) * 128];
__device__ __half   g_xw16[(size_t)R * NPAD * HOUT];    // xw in fp16 (164 MB)
__device__ float    g_qn[(size_t)R * NN * HEADS];
__device__ float    g_kn[(size_t)R * NN * HEADS];
__device__ float    g_alphas[(size_t)EE * HEADS];       // sorted-order logits
__device__ int      g_cnt[NN];
__device__ int      g_off[NN + 1];
__device__ int      g_woff[NN];
__device__ int      g_esort[EE];                        // src | (rel<<16)
__device__ int      g_bsum[20];
__device__ int      g_bofs[20];

// ---------------- side stream + events (created before harness checkpoints)
static cudaStream_t g_s2;
static cudaEvent_t  g_evF, g_evH, g_evJ;
namespace {
struct StreamInit {
    StreamInit() {
        cudaStreamCreateWithFlags(&g_s2, cudaStreamNonBlocking);
        cudaEventCreateWithFlags(&g_evF, cudaEventDisableTiming);
        cudaEventCreateWithFlags(&g_evH, cudaEventDisableTiming);
        cudaEventCreateWithFlags(&g_evJ, cudaEventDisableTiming);
    }
};
StreamInit g_streaminit;
}

// ---------------- small helpers -------------------------------------------
__device__ __forceinline__ uint32_t smem_u32(const void* p) {
    uint32_t a;
    asm("{ .reg .u64 t; cvta.to.shared.u64 t, %1; cvt.u32.u64 %0, t; }"
        : "=r"(a) : "l"(p));
    return a;
}
__device__ __forceinline__ void cp16(uint32_t dst, const void* src) {
    asm volatile("cp.async.cg.shared.global [%0], [%1], 16;"
                 :: "r"(dst), "l"(src) : "memory");
}
#define CP_COMMIT() asm volatile("cp.async.commit_group;" ::: "memory")
#define CP_WAIT1()  asm volatile("cp.async.wait_group 1;" ::: "memory")

__device__ __forceinline__ uint32_t packh2(float a, float b) {
    __half2 h = __floats2half2_rn(a, b);
    return *reinterpret_cast<uint32_t*>(&h);
}

// ---------------- 1. build split fp16 h ------------------------------------
__global__ void build_h_kernel(const float* __restrict__ x,
                               const int* __restrict__ nt,
                               const float* __restrict__ type_emb) {
    int idx = blockIdx.x * blockDim.x + threadIdx.x;   // float4 index over NPAD rows
    const int per_row = F_IN / 4;                      // 80
    if (idx >= NPAD * per_row) return;
    int n  = idx / per_row;
    int c4 = idx - n * per_row;
    float4 v = make_float4(0.f, 0.f, 0.f, 0.f);
    if (n < NN) {
        if (c4 < IN_CH / 4) v = *(const float4*)&x[(size_t)n * IN_CH + c4 * 4];
        else {
            int t = nt[n];
            v = *(const float4*)&type_emb[(size_t)t * TYPE_DIM + (c4 - IN_CH / 4) * 4];
        }
    }
    __half2 p0 = __floats2half2_rn(v.x, v.y);
    __half2 p1 = __floats2half2_rn(v.z, v.w);
    ((__half2*)g_h16)[idx * 2 + 0] = p0;
    ((__half2*)g_h16)[idx * 2 + 1] = p1;
    float2 f0 = __half22float2(p0), f1 = __half22float2(p1);
    ((__half2*)g_h16lo)[idx * 2 + 0] = __floats2half2_rn(v.x - f0.x, v.y - f0.y);
    ((__half2*)g_h16lo)[idx * 2 + 1] = __floats2half2_rn(v.z - f1.x, v.w - f1.y);
}

// ---------------- 1b. convert W -> packed half2 k-pairs --------------------
__global__ void convert_w_kernel(const float* __restrict__ W) {
    int idx = blockIdx.x * blockDim.x + threadIdx.x;   // [r][kk][n]
    if (idx >= R * (F_IN / 2) * HOUT) return;
    int r = idx / ((F_IN / 2) * HOUT);
    int rem = idx - r * ((F_IN / 2) * HOUT);
    int kk = rem >> 9;
    int n  = rem & 511;
    float v0 = W[((size_t)r * F_IN + 2 * kk) * HOUT + n];
    float v1 = W[((size_t)r * F_IN + 2 * kk + 1) * HOUT + n];
    g_w16p[idx] = packh2(v0, v1);
}

// ---------------- 1c. fused q/k weights ------------------------------------
__global__ __launch_bounds__(320)
void fuse_w_kernel(const float* __restrict__ W,
                   const float* __restrict__ attq, const float* __restrict__ attk) {
    int r = blockIdx.x;
    __shared__ float att_s[16][HOUT];
    int tid = threadIdx.x;
    for (int i = tid; i < HOUT * HEADS; i += 320) {
        int c = i >> 3, h = i & 7;
        att_s[h][c]     = attq[((size_t)r * HOUT + c) * HEADS + h];
        att_s[8 + h][c] = attk[((size_t)r * HOUT + c) * HEADS + h];
    }
    __syncthreads();
    int f = tid;
    const float* wrow = W + ((size_t)r * F_IN + f) * HOUT;
    float acc[16];
    #pragma unroll
    for (int p = 0; p < 16; p++) acc[p] = 0.0f;
    for (int c = 0; c < HOUT; c += 4) {
        float4 w = *(const float4*)&wrow[c];
        #pragma unroll
        for (int p = 0; p < 16; p++) {
            float4 a = *(const float4*)&att_s[p][c];
            acc[p] += w.x * a.x + w.y * a.y + w.z * a.z + w.w * a.w;
        }
    }
    #pragma unroll
    for (int p = 0; p < 16; p++)
        g_wqk[((size_t)r * 16 + p) * F_IN + f] = acc[p];
}

// ---------------- 1d. split Wqk into hi/lo packed --------------------------
__global__ void split_wqk_kernel() {
    int idx = blockIdx.x * blockDim.x + threadIdx.x;
    if (idx >= (F_IN / 2) * 128) return;
    int kk = idx >> 7;
    int c  = idx & 127;
    float v0 = g_wqk[(size_t)c * F_IN + 2 * kk];
    float v1 = g_wqk[(size_t)c * F_IN + 2 * kk + 1];
    __half h0 = __float2half_rn(v0);
    __half h1 = __float2half_rn(v1);
    g_wqk16h[idx] = packh2(__half2float(h0), __half2float(h1));
    g_wqk16l[idx] = packh2(v0 - __half2float(h0), v1 - __half2float(h1));
}

// ---------------- 2. qn/kn via split-fp16 GEMM (f32 accum, exact logits) ---
#define AROW 12      // u32 per A smem row (48B)
#define BROW 136     // u32 per B smem row (544B)

__global__ __launch_bounds__(256)
void qkgemm_kernel() {
    __shared__ __align__(16) uint32_t Ah[2][128 * AROW];
    __shared__ __align__(16) uint32_t Al[2][128 * AROW];
    __shared__ __align__(16) uint32_t Bh[2][8 * BROW];
    __shared__ __align__(16) uint32_t Bl[2][8 * BROW];
    int tid = threadIdx.x, wid = tid >> 5, lane = tid & 31;
    int gid = lane >> 2, t = lane & 3;
    int wm = wid >> 1, wn = wid & 1;
    int rowBase = blockIdx.x * 128;
    uint32_t ahA = smem_u32(Ah), alA = smem_u32(Al);
    uint32_t bhA = smem_u32(Bh), blA = smem_u32(Bl);

    float acc[2][8][4];
    #pragma unroll
    for (int i = 0; i < 2; i++)
        #pragma unroll
        for (int j = 0; j < 8; j++)
            #pragma unroll
            for (int q = 0; q < 4; q++) acc[i][j][q] = 0.0f;

    auto fill = [&](int buf, int kc) {
        int k0 = kc * 16;
        int row = tid >> 1, hf = tid & 1;
        cp16(ahA + buf * (128 * AROW * 4) + row * 48 + hf * 16,
             g_h16 + (size_t)(rowBase + row) * F_IN + k0 + hf * 8);
        cp16(alA + buf * (128 * AROW * 4) + row * 48 + hf * 16,
             g_h16lo + (size_t)(rowBase + row) * F_IN + k0 + hf * 8);
        int kk = tid >> 5, seg = tid & 31;
        cp16(bhA + buf * (8 * BROW * 4) + kk * 544 + seg * 16,
             g_wqk16h + (kc * 8 + kk) * 128 + seg * 4);
        cp16(blA + buf * (8 * BROW * 4) + kk * 544 + seg * 16,
             g_wqk16l + (kc * 8 + kk) * 128 + seg * 4);
    };

    fill(0, 0); CP_COMMIT();
    for (int kc = 0; kc < 20; kc++) {
        if (kc + 1 < 20) fill((kc + 1) & 1, kc + 1);
        CP_COMMIT();
        CP_WAIT1();
        __syncthreads();
        int buf = kc & 1;
        uint32_t bh[8][2], bl[8][2];
        #pragma unroll
        for (int na = 0; na < 8; na++) {
            int n = wn * 64 + na * 8 + gid;
            bh[na][0] = Bh[buf][t * BROW + n];
            bh[na][1] = Bh[buf][(t + 4) * BROW + n];
            bl[na][0] = Bl[buf][t * BROW + n];
            bl[na][1] = Bl[buf][(t + 4) * BROW + n];
        }
        #pragma unroll
        for (int ma = 0; ma < 2; ma++) {
            int m = wm * 32 + ma * 16 + gid;
            uint32_t a0 = Ah[buf][m * AROW + t],       a1 = Ah[buf][(m + 8) * AROW + t];
            uint32_t a2 = Ah[buf][m * AROW + t + 4],   a3 = Ah[buf][(m + 8) * AROW + t + 4];
            uint32_t c0 = Al[buf][m * AROW + t],       c1 = Al[buf][(m + 8) * AROW + t];
            uint32_t c2 = Al[buf][m * AROW + t + 4],   c3 = Al[buf][(m + 8) * AROW + t + 4];
            #pragma unroll
            for (int na = 0; na < 8; na++) {
                asm volatile("mma.sync.aligned.m16n8k16.row.col.f32.f16.f16.f32 "
                    "{%0,%1,%2,%3}, {%4,%5,%6,%7}, {%8,%9}, {%0,%1,%2,%3};"
                    : "+f"(acc[ma][na][0]), "+f"(acc[ma][na][1]),
                      "+f"(acc[ma][na][2]), "+f"(acc[ma][na][3])
                    : "r"(a0), "r"(a1), "r"(a2), "r"(a3), "r"(bh[na][0]), "r"(bh[na][1]));
                asm volatile("mma.sync.aligned.m16n8k16.row.col.f32.f16.f16.f32 "
                    "{%0,%1,%2,%3}, {%4,%5,%6,%7}, {%8,%9}, {%0,%1,%2,%3};"
                    : "+f"(acc[ma][na][0]), "+f"(acc[ma][na][1]),
                      "+f"(acc[ma][na][2]), "+f"(acc[ma][na][3])
                    : "r"(a0), "r"(a1), "r"(a2), "r"(a3), "r"(bl[na][0]), "r"(bl[na][1]));
                asm volatile("mma.sync.aligned.m16n8k16.row.col.f32.f16.f16.f32 "
                    "{%0,%1,%2,%3}, {%4,%5,%6,%7}, {%8,%9}, {%0,%1,%2,%3};"
                    : "+f"(acc[ma][na][0]), "+f"(acc[ma][na][1]),
                      "+f"(acc[ma][na][2]), "+f"(acc[ma][na][3])
                    : "r"(c0), "r"(c1), "r"(c2), "r"(c3), "r"(bh[na][0]), "r"(bh[na][1]));
            }
        }
        __syncthreads();
    }
    #pragma unroll
    for (int ma = 0; ma < 2; ma++) {
        int row0 = rowBase + wm * 32 + ma * 16 + gid;
        #pragma unroll
        for (int na = 0; na < 8; na++) {
            int c = wn * 64 + na * 8 + 2 * t;
            int rr = c >> 4, p = c & 15;
            float* base = (p < 8) ? g_qn : g_kn;
            int pp = p & 7;
            if (row0 < NN) {
                float* d0 = base + ((size_t)rr * NN + row0) * HEADS + pp;
                d0[0] = acc[ma][na][0]; d0[1] = acc[ma][na][1];
            }
            if (row0 + 8 < NN) {
                float* d1 = base + ((size_t)rr * NN + row0 + 8) * HEADS + pp;
                d1[0] = acc[ma][na][2]; d1[1] = acc[ma][na][3];
            }
        }
    }
}

// ---------------- 3. xw16 = h16 @ W16  (f16-accum mma + fp32 promotion) ----
#define ASZ (128 * AROW)   // u32 per stage
#define BSZ (8 * BROW)

__global__ __launch_bounds__(256, 2)
void gemm_f16_kernel() {
    __shared__ __align__(16) uint32_t As[3][ASZ];   // 18432 B
    __shared__ __align__(16) uint32_t Bs[3][BSZ];   // 13056 B
    __shared__ __align__(16) uint32_t Es[64 * 68];  // 17408 B
    int tid = threadIdx.x, wid = tid >> 5, lane = tid & 31;
    int gid = lane >> 2, t = lane & 3;
    int wm = wid >> 1, wn = wid & 1;
    int mtile = blockIdx.x, ntile = blockIdx.y, r = blockIdx.z;
    int rowBase = mtile * 128;
    uint32_t aA = smem_u32(As), bA = smem_u32(Bs);

    float acc[2][8][4];
    #pragma unroll
    for (int i = 0; i < 2; i++)
        #pragma unroll
        for (int j = 0; j < 8; j++)
            #pragma unroll
            for (int q = 0; q < 4; q++) acc[i][j][q] = 0.0f;

    auto fill = [&](int buf, int kc) {
        int k0 = kc * 16;
        int row = tid >> 1, hf = tid & 1;
        cp16(aA + buf * (ASZ * 4) + row * 48 + hf * 16,
             g_h16 + (size_t)(rowBase + row) * F_IN + k0 + hf * 8);
        int kk = tid >> 5, seg = tid & 31;
        cp16(bA + buf * (BSZ * 4) + kk * 544 + seg * 16,
             g_w16p + ((size_t)r * (F_IN / 2) + kc * 8 + kk) * HOUT + ntile * 128 + seg * 4);
    };

    fill(0, 0); CP_COMMIT();
    fill(1, 1); CP_COMMIT();

    uint32_t arow_off = (lane & 15) * 48 + (lane >> 4) * 16;

    for (int kc = 0; kc < 20; kc++) {
        CP_WAIT1();
        __syncthreads();
        if (kc + 2 < 20) fill((kc + 2) % 3, kc + 2);
        CP_COMMIT();
        int buf = kc % 3;
        uint32_t bf[8][2];
        #pragma unroll
        for (int na = 0; na < 8; na++) {
            int n = wn * 64 + na * 8 + gid;
            bf[na][0] = Bs[buf][t * BROW + n];
            bf[na][1] = Bs[buf][(t + 4) * BROW + n];
        }
        #pragma unroll
        for (int ma = 0; ma < 2; ma++) {
            uint32_t a0, a1, a2, a3;
            uint32_t addr = aA + buf * (ASZ * 4) + (wm * 32 + ma * 16) * 48 + arow_off;
            asm volatile("ldmatrix.sync.aligned.m8n8.x4.shared.b16 {%0,%1,%2,%3}, [%4];"
                         : "=r"(a0), "=r"(a1), "=r"(a2), "=r"(a3) : "r"(addr));
            #pragma unroll
            for (int na = 0; na < 8; na++) {
                uint32_t h0 = 0, h1 = 0;
                asm volatile("mma.sync.aligned.m16n8k16.row.col.f16.f16.f16.f16 "
                    "{%0,%1}, {%2,%3,%4,%5}, {%6,%7}, {%0,%1};"
                    : "+r"(h0), "+r"(h1)
                    : "r"(a0), "r"(a1), "r"(a2), "r"(a3),
                      "r"(bf[na][0]), "r"(bf[na][1]));
                float2 f0 = __half22float2(*(__half2*)&h0);
                float2 f1 = __half22float2(*(__half2*)&h1);
                acc[ma][na][0] += f0.x; acc[ma][na][1] += f0.y;
                acc[ma][na][2] += f1.x; acc[ma][na][3] += f1.y;
            }
        }
    }

    // staged fp16 epilogue, two halves of 64 rows
    uint32_t* dstb = (uint32_t*)g_xw16 + (size_t)r * NPAD * (HOUT / 2);
    for (int h2 = 0; h2 < 2; h2++) {
        __syncthreads();
        if ((wm >> 1) == h2) {
            int blr = (wm & 1) * 32;
            #pragma unroll
            for (int ma = 0; ma < 2; ma++) {
                int lr = blr + ma * 16 + gid;
                #pragma unroll
                for (int na = 0; na < 8; na++) {
                    int col = wn * 32 + na * 4 + t;
                    Es[lr * 68 + col]       = packh2(acc[ma][na][0], acc[ma][na][1]);
                    Es[(lr + 8) * 68 + col] = packh2(acc[ma][na][2], acc[ma][na][3]);
                }
            }
        }
        __syncthreads();
        #pragma unroll
        for (int j = 0; j < 4; j++) {
            int i = j * 256 + tid;
            int row = i >> 4, c4 = i & 15;
            int grow = rowBase + h2 * 64 + row;
            uint4 v = *(uint4*)&Es[row * 68 + c4 * 4];
            *(uint4*)&dstb[(size_t)grow * (HOUT / 2) + ntile * 64 + c4 * 4] = v;
        }
    }
}

// ---------------- 4. counting sort (parallel scan) -------------------------
__global__ void hist_kernel(const int* __restrict__ ei) {
    int e = blockIdx.x * blockDim.x + threadIdx.x;
    if (e >= EE) return;
    atomicAdd(&g_cnt[ei[EE + e]], 1);
}

__global__ void scan1_kernel() {
    __shared__ int sd[1024];
    int b = blockIdx.x, tid = threadIdx.x, i = b * 1024 + tid;
    int v = (i < NN) ? g_cnt[i] : 0;
    sd[tid] = v;
    __syncthreads();
    for (int o = 1; o < 1024; o <<= 1) {
        int tv = (tid >= o) ? sd[tid - o] : 0;
        __syncthreads();
        sd[tid] += tv;
        __syncthreads();
    }
    if (i < NN) g_off[i + 1] = sd[tid];
    if (tid == 1023) g_bsum[b] = sd[1023];
}

__global__ void scan2_kernel() {
    int tid = threadIdx.x;   // 32
    int v = (tid < 20) ? g_bsum[tid] : 0;
    for (int o = 1; o < 32; o <<= 1) {
        int tv = __shfl_up_sync(0xFFFFFFFF, v, o);
        if (tid >= o) v += tv;
    }
    if (tid < 20) g_bofs[tid] = v - g_bsum[tid];
}

__global__ void scan3_kernel() {
    int b = blockIdx.x, i = b * 1024 + threadIdx.x;
    if (i < NN) g_off[i + 1] += g_bofs[b];
    if (i == 0) g_off[0] = 0;
}

__global__ void copy_woff_kernel() {
    int i = blockIdx.x * blockDim.x + threadIdx.x;
    if (i < NN) g_woff[i] = g_off[i];
}

// ---------------- 5. scatter + edge logits ---------------------------------
__global__ __launch_bounds__(256)
void scatter_kernel(const int* __restrict__ ei, const int* __restrict__ et) {
    int e = blockIdx.x * blockDim.x + threadIdx.x;
    if (e >= EE) return;
    int s = ei[e];
    int d = ei[EE + e];
    int r = et[e];
    int pos = atomicAdd(&g_woff[d], 1);
    g_esort[pos] = s | (r << 16);
    const float* q = g_qn + ((size_t)r * NN + d) * HEADS;
    const float* k = g_kn + ((size_t)r * NN + s) * HEADS;
    float4 q0 = *(const float4*)q,     q1 = *(const float4*)(q + 4);
    float4 k0 = *(const float4*)k,     k1 = *(const float4*)(k + 4);
    float a[8] = { q0.x + k0.x, q0.y + k0.y, q0.z + k0.z, q0.w + k0.w,
                   q1.x + k1.x, q1.y + k1.y, q1.z + k1.z, q1.w + k1.w };
    #pragma unroll
    for (int h = 0; h < 8; h++) a[h] = a[h] > 0.f ? a[h] : 0.2f * a[h];
    float* ap = g_alphas + (size_t)pos * HEADS;
    *(float4*)ap       = make_float4(a[0], a[1], a[2], a[3]);
    *(float4*)(ap + 4) = make_float4(a[4], a[5], a[6], a[7]);
}

// ---------------- 6. fused softmax + aggregate + bias + relu ---------------
__global__ __launch_bounds__(256)
void agg_fused_kernel(const float* __restrict__ bias, float* __restrict__ out) {
    int d = (blockIdx.x * 256 + threadIdx.x) >> 5;
    int lane = threadIdx.x & 31;
    if (d >= NN) return;
    int h = lane >> 2, t = lane & 3;
    int beg = g_off[d], end = g_off[d + 1];

    // single sum pass (logits bounded, max-subtraction unnecessary)
    float ss = 0.f;
    for (int e = beg + t; e < end; e += 4)
        ss += expf(g_alphas[(size_t)e * HEADS + h]);
    ss += __shfl_xor_sync(0xFFFFFFFF, ss, 1);
    ss += __shfl_xor_sync(0xFFFFFFFF, ss, 2);
    float inv = 1.f / (ss + 1e-16f);

    float acc[16];
    #pragma unroll
    for (int j = 0; j < 16; j++) acc[j] = 0.f;

    // weighted gather, 4 edges/iter for deep MLP
    int e = beg;
    for (; e + 3 < end; e += 4) {
        int   p[4];
        float al[4];
        uint4 u0[4], u1[4];
        #pragma unroll
        for (int i = 0; i < 4; i++) {
            p[i]  = g_esort[e + i];
            al[i] = g_alphas[(size_t)(e + i) * HEADS + h];
        }
        #pragma unroll
        for (int i = 0; i < 4; i++) {
            const uint4* rp = (const uint4*)(g_xw16 +
                ((size_t)(p[i] >> 16) * NPAD + (p[i] & 0xFFFF)) * HOUT + lane * 16);
            u0[i] = rp[0];
            u1[i] = rp[1];
        }
        #pragma unroll
        for (int i = 0; i < 4; i++) {
            float w = expf(al[i]) * inv;
            const __half2* x0 = (const __half2*)&u0[i];
            const __half2* x1 = (const __half2*)&u1[i];
            #pragma unroll
            for (int j = 0; j < 4; j++) {
                float2 f = __half22float2(x0[j]);
                acc[2 * j]     += w * f.x;
                acc[2 * j + 1] += w * f.y;
            }
            #pragma unroll
            for (int j = 0; j < 4; j++) {
                float2 f = __half22float2(x1[j]);
                acc[8 + 2 * j]     += w * f.x;
                acc[8 + 2 * j + 1] += w * f.y;
            }
        }
    }
    for (; e < end; e++) {
        int p = g_esort[e];
        float a = g_alphas[(size_t)e * HEADS + h];
        const uint4* rp = (const uint4*)(g_xw16 +
            ((size_t)(p >> 16) * NPAD + (p & 0xFFFF)) * HOUT + lane * 16);
        uint4 u0 = rp[0], u1 = rp[1];
        float w = expf(a) * inv;
        const __half2* x0 = (const __half2*)&u0;
        const __half2* x1 = (const __half2*)&u1;
        #pragma unroll
        for (int j = 0; j < 4; j++) {
            float2 f = __half22float2(x0[j]);
            acc[2 * j]     += w * f.x;
            acc[2 * j + 1] += w * f.y;
        }
        #pragma unroll
        for (int j = 0; j < 4; j++) {
            float2 f = __half22float2(x1[j]);
            acc[8 + 2 * j]     += w * f.x;
            acc[8 + 2 * j + 1] += w * f.y;
        }
    }

    float* orow = out + (size_t)d * HOUT + lane * 16;
    const float4* brow = (const float4*)(bias + lane * 16);
    #pragma unroll
    for (int j4 = 0; j4 < 4; j4++) {
        float4 b = brow[j4];
        float4 v = make_float4(fmaxf(acc[4 * j4 + 0] + b.x, 0.f),
                               fmaxf(acc[4 * j4 + 1] + b.y, 0.f),
                               fmaxf(acc[4 * j4 + 2] + b.z, 0.f),
                               fmaxf(acc[4 * j4 + 3] + b.w, 0.f));
        ((float4*)orow)[j4] = v;
    }
}

// ---------------- launch ---------------------------------------------------
extern "C" void kernel_launch(void* const* d_in, const int* in_sizes, int n_in,
                              void* d_out, int out_size) {
    const float* x        = (const float*)d_in[0];
    const int*   nt       = (const int*)  d_in[1];
    const int*   ei       = (const int*)  d_in[2];
    const int*   et       = (const int*)  d_in[3];
    const float* type_emb = (const float*)d_in[4];
    const float* weight   = (const float*)d_in[5];
    const float* att_q    = (const float*)d_in[6];
    const float* att_k    = (const float*)d_in[7];
    const float* bias     = (const float*)d_in[8];
    float* out = (float*)d_out;

    void* cnt_addr = nullptr;  cudaGetSymbolAddress(&cnt_addr, g_cnt);

    // fork side stream
    cudaEventRecord(g_evF, 0);
    cudaStreamWaitEvent(g_s2, g_evF, 0);

    // ---- stream 0: build inputs for GEMM, then GEMM ----
    {
        int total = NPAD * (F_IN / 4);
        build_h_kernel<<<(total + 255) / 256, 256>>>(x, nt, type_emb);
    }
    {
        int total = R * (F_IN / 2) * HOUT;
        convert_w_kernel<<<(total + 255) / 256, 256>>>(weight);
    }
    cudaEventRecord(g_evH, 0);
    {
        dim3 grid(NPAD / 128, HOUT / 128, R);
        gemm_f16_kernel<<<grid, 256>>>();
    }

    // ---- side stream: CSR + qk weights + qkgemm + scatter ----
    cudaMemsetAsync(cnt_addr, 0, NN * sizeof(int), g_s2);
    hist_kernel<<<(EE + 255) / 256, 256, 0, g_s2>>>(ei);
    scan1_kernel<<<20, 1024, 0, g_s2>>>();
    scan2_kernel<<<1, 32, 0, g_s2>>>();
    scan3_kernel<<<20, 1024, 0, g_s2>>>();
    copy_woff_kernel<<<(NN + 255) / 256, 256, 0, g_s2>>>();
    fuse_w_kernel<<<R, 320, 0, g_s2>>>(weight, att_q, att_k);
    {
        int total = (F_IN / 2) * 128;
        split_wqk_kernel<<<(total + 255) / 256, 256, 0, g_s2>>>();
    }
    cudaStreamWaitEvent(g_s2, g_evH, 0);          // qkgemm needs h16
    qkgemm_kernel<<<NPAD / 128, 256, 0, g_s2>>>();
    scatter_kernel<<<(EE + 255) / 256, 256, 0, g_s2>>>(ei, et);
    cudaEventRecord(g_evJ, g_s2);

    // ---- join + final aggregation ----
    cudaStreamWaitEvent(0, g_evJ, 0);
    agg_fused_kernel<<<(NN * 32) / 256, 256>>>(bias, out);
}

// round 12
// speedup vs baseline: 1.1807x; 1.1807x over previous
#include <cuda_runtime.h>
#include <cuda_fp16.h>
#include <math.h>
#include <stdint.h>

// Problem constants
#define NN    20000
#define NPAD  20096      // 157 * 128, padded M for GEMM tiles
#define EE    320000
#define IN_CH 256
#define TYPE_DIM 64
#define F_IN  320
#define R     8
#define HEADS 8
#define HOUT  512

// ---------------- scratch (device globals) --------------------------------
__device__ __half   g_h16[(size_t)NPAD * F_IN];         // fp16 hi part
__device__ __half   g_h16lo[(size_t)NPAD * F_IN];       // fp16 residual
__device__ uint32_t g_w16p[(size_t)R * (F_IN / 2) * HOUT];  // W packed k-pairs half2
__device__ float    g_wqk[(size_t)R * 16 * F_IN];       // fused q/k weights
__device__ uint32_t g_wqk16h[(F_IN / 2) * 128];
__device__ uint32_t g_wqk16l[(F_IN / 2) * 128];
__device__ __half   g_xw16[(size_t)R * NPAD * HOUT];    // xw in fp16 (164 MB)
__device__ float    g_qn[(size_t)R * NN * HEADS];
__device__ float    g_kn[(size_t)R * NN * HEADS];
__device__ float    g_alphas[(size_t)EE * HEADS];       // sorted-order logits
__device__ int      g_cnt[NN];
__device__ int      g_off[NN + 1];
__device__ int      g_woff[NN];
__device__ int      g_esort[EE];                        // src | (rel<<16)
__device__ int      g_bsum[20];
__device__ int      g_bofs[20];

// ---------------- side streams + events (created before harness checkpoints)
static cudaStream_t g_s2, g_s3;
static cudaEvent_t  g_evF, g_evH, g_evJ, g_evW;
namespace {
struct StreamInit {
    StreamInit() {
        cudaStreamCreateWithFlags(&g_s2, cudaStreamNonBlocking);
        cudaStreamCreateWithFlags(&g_s3, cudaStreamNonBlocking);
        cudaEventCreateWithFlags(&g_evF, cudaEventDisableTiming);
        cudaEventCreateWithFlags(&g_evH, cudaEventDisableTiming);
        cudaEventCreateWithFlags(&g_evJ, cudaEventDisableTiming);
        cudaEventCreateWithFlags(&g_evW, cudaEventDisableTiming);
    }
};
StreamInit g_streaminit;
}

// ---------------- small helpers -------------------------------------------
__device__ __forceinline__ uint32_t smem_u32(const void* p) {
    uint32_t a;
    asm("{ .reg .u64 t; cvta.to.shared.u64 t, %1; cvt.u32.u64 %0, t; }"
        : "=r"(a) : "l"(p));
    return a;
}
__device__ __forceinline__ void cp16(uint32_t dst, const void* src) {
    asm volatile("cp.async.cg.shared.global [%0], [%1], 16;"
                 :: "r"(dst), "l"(src) : "memory");
}
#define CP_COMMIT() asm volatile("cp.async.commit_group;" ::: "memory")
#define CP_WAIT1()  asm volatile("cp.async.wait_group 1;" ::: "memory")

__device__ __forceinline__ uint32_t packh2(float a, float b) {
    __half2 h = __floats2half2_rn(a, b);
    return *reinterpret_cast<uint32_t*>(&h);
}

// ---------------- 1. build split fp16 h ------------------------------------
__global__ void build_h_kernel(const float* __restrict__ x,
                               const int* __restrict__ nt,
                               const float* __restrict__ type_emb) {
    int idx = blockIdx.x * blockDim.x + threadIdx.x;   // float4 index over NPAD rows
    const int per_row = F_IN / 4;                      // 80
    if (idx >= NPAD * per_row) return;
    int n  = idx / per_row;
    int c4 = idx - n * per_row;
    float4 v = make_float4(0.f, 0.f, 0.f, 0.f);
    if (n < NN) {
        if (c4 < IN_CH / 4) v = *(const float4*)&x[(size_t)n * IN_CH + c4 * 4];
        else {
            int t = nt[n];
            v = *(const float4*)&type_emb[(size_t)t * TYPE_DIM + (c4 - IN_CH / 4) * 4];
        }
    }
    __half2 p0 = __floats2half2_rn(v.x, v.y);
    __half2 p1 = __floats2half2_rn(v.z, v.w);
    ((__half2*)g_h16)[idx * 2 + 0] = p0;
    ((__half2*)g_h16)[idx * 2 + 1] = p1;
    float2 f0 = __half22float2(p0), f1 = __half22float2(p1);
    ((__half2*)g_h16lo)[idx * 2 + 0] = __floats2half2_rn(v.x - f0.x, v.y - f0.y);
    ((__half2*)g_h16lo)[idx * 2 + 1] = __floats2half2_rn(v.z - f1.x, v.w - f1.y);
}

// ---------------- 1b. convert W -> packed half2 k-pairs --------------------
__global__ void convert_w_kernel(const float* __restrict__ W) {
    int idx = blockIdx.x * blockDim.x + threadIdx.x;   // [r][kk][n]
    if (idx >= R * (F_IN / 2) * HOUT) return;
    int r = idx / ((F_IN / 2) * HOUT);
    int rem = idx - r * ((F_IN / 2) * HOUT);
    int kk = rem >> 9;
    int n  = rem & 511;
    float v0 = W[((size_t)r * F_IN + 2 * kk) * HOUT + n];
    float v1 = W[((size_t)r * F_IN + 2 * kk + 1) * HOUT + n];
    g_w16p[idx] = packh2(v0, v1);
}

// ---------------- 1c. fused q/k weights ------------------------------------
__global__ __launch_bounds__(320)
void fuse_w_kernel(const float* __restrict__ W,
                   const float* __restrict__ attq, const float* __restrict__ attk) {
    int r = blockIdx.x;
    __shared__ float att_s[16][HOUT];
    int tid = threadIdx.x;
    for (int i = tid; i < HOUT * HEADS; i += 320) {
        int c = i >> 3, h = i & 7;
        att_s[h][c]     = attq[((size_t)r * HOUT + c) * HEADS + h];
        att_s[8 + h][c] = attk[((size_t)r * HOUT + c) * HEADS + h];
    }
    __syncthreads();
    int f = tid;
    const float* wrow = W + ((size_t)r * F_IN + f) * HOUT;
    float acc[16];
    #pragma unroll
    for (int p = 0; p < 16; p++) acc[p] = 0.0f;
    for (int c = 0; c < HOUT; c += 4) {
        float4 w = *(const float4*)&wrow[c];
        #pragma unroll
        for (int p = 0; p < 16; p++) {
            float4 a = *(const float4*)&att_s[p][c];
            acc[p] += w.x * a.x + w.y * a.y + w.z * a.z + w.w * a.w;
        }
    }
    #pragma unroll
    for (int p = 0; p < 16; p++)
        g_wqk[((size_t)r * 16 + p) * F_IN + f] = acc[p];
}

// ---------------- 1d. split Wqk into hi/lo packed --------------------------
__global__ void split_wqk_kernel() {
    int idx = blockIdx.x * blockDim.x + threadIdx.x;
    if (idx >= (F_IN / 2) * 128) return;
    int kk = idx >> 7;
    int c  = idx & 127;
    float v0 = g_wqk[(size_t)c * F_IN + 2 * kk];
    float v1 = g_wqk[(size_t)c * F_IN + 2 * kk + 1];
    __half h0 = __float2half_rn(v0);
    __half h1 = __float2half_rn(v1);
    g_wqk16h[idx] = packh2(__half2float(h0), __half2float(h1));
    g_wqk16l[idx] = packh2(v0 - __half2float(h0), v1 - __half2float(h1));
}

// ---------------- 2. qn/kn via split-fp16 GEMM (f32 accum, exact logits) ---
#define AROW 12      // u32 per A smem row (48B)
#define BROW 136     // u32 per B smem row (544B)

__global__ __launch_bounds__(256)
void qkgemm_kernel() {
    __shared__ __align__(16) uint32_t Ah[2][128 * AROW];
    __shared__ __align__(16) uint32_t Al[2][128 * AROW];
    __shared__ __align__(16) uint32_t Bh[2][8 * BROW];
    __shared__ __align__(16) uint32_t Bl[2][8 * BROW];
    int tid = threadIdx.x, wid = tid >> 5, lane = tid & 31;
    int gid = lane >> 2, t = lane & 3;
    int wm = wid >> 1, wn = wid & 1;
    int rowBase = blockIdx.x * 128;
    uint32_t ahA = smem_u32(Ah), alA = smem_u32(Al);
    uint32_t bhA = smem_u32(Bh), blA = smem_u32(Bl);

    float acc[2][8][4];
    #pragma unroll
    for (int i = 0; i < 2; i++)
        #pragma unroll
        for (int j = 0; j < 8; j++)
            #pragma unroll
            for (int q = 0; q < 4; q++) acc[i][j][q] = 0.0f;

    auto fill = [&](int buf, int kc) {
        int k0 = kc * 16;
        int row = tid >> 1, hf = tid & 1;
        cp16(ahA + buf * (128 * AROW * 4) + row * 48 + hf * 16,
             g_h16 + (size_t)(rowBase + row) * F_IN + k0 + hf * 8);
        cp16(alA + buf * (128 * AROW * 4) + row * 48 + hf * 16,
             g_h16lo + (size_t)(rowBase + row) * F_IN + k0 + hf * 8);
        int kk = tid >> 5, seg = tid & 31;
        cp16(bhA + buf * (8 * BROW * 4) + kk * 544 + seg * 16,
             g_wqk16h + (kc * 8 + kk) * 128 + seg * 4);
        cp16(blA + buf * (8 * BROW * 4) + kk * 544 + seg * 16,
             g_wqk16l + (kc * 8 + kk) * 128 + seg * 4);
    };

    fill(0, 0); CP_COMMIT();
    for (int kc = 0; kc < 20; kc++) {
        if (kc + 1 < 20) fill((kc + 1) & 1, kc + 1);
        CP_COMMIT();
        CP_WAIT1();
        __syncthreads();
        int buf = kc & 1;
        uint32_t bh[8][2], bl[8][2];
        #pragma unroll
        for (int na = 0; na < 8; na++) {
            int n = wn * 64 + na * 8 + gid;
            bh[na][0] = Bh[buf][t * BROW + n];
            bh[na][1] = Bh[buf][(t + 4) * BROW + n];
            bl[na][0] = Bl[buf][t * BROW + n];
            bl[na][1] = Bl[buf][(t + 4) * BROW + n];
        }
        #pragma unroll
        for (int ma = 0; ma < 2; ma++) {
            int m = wm * 32 + ma * 16 + gid;
            uint32_t a0 = Ah[buf][m * AROW + t],       a1 = Ah[buf][(m + 8) * AROW + t];
            uint32_t a2 = Ah[buf][m * AROW + t + 4],   a3 = Ah[buf][(m + 8) * AROW + t + 4];
            uint32_t c0 = Al[buf][m * AROW + t],       c1 = Al[buf][(m + 8) * AROW + t];
            uint32_t c2 = Al[buf][m * AROW + t + 4],   c3 = Al[buf][(m + 8) * AROW + t + 4];
            #pragma unroll
            for (int na = 0; na < 8; na++) {
                asm volatile("mma.sync.aligned.m16n8k16.row.col.f32.f16.f16.f32 "
                    "{%0,%1,%2,%3}, {%4,%5,%6,%7}, {%8,%9}, {%0,%1,%2,%3};"
                    : "+f"(acc[ma][na][0]), "+f"(acc[ma][na][1]),
                      "+f"(acc[ma][na][2]), "+f"(acc[ma][na][3])
                    : "r"(a0), "r"(a1), "r"(a2), "r"(a3), "r"(bh[na][0]), "r"(bh[na][1]));
                asm volatile("mma.sync.aligned.m16n8k16.row.col.f32.f16.f16.f32 "
                    "{%0,%1,%2,%3}, {%4,%5,%6,%7}, {%8,%9}, {%0,%1,%2,%3};"
                    : "+f"(acc[ma][na][0]), "+f"(acc[ma][na][1]),
                      "+f"(acc[ma][na][2]), "+f"(acc[ma][na][3])
                    : "r"(a0), "r"(a1), "r"(a2), "r"(a3), "r"(bl[na][0]), "r"(bl[na][1]));
                asm volatile("mma.sync.aligned.m16n8k16.row.col.f32.f16.f16.f32 "
                    "{%0,%1,%2,%3}, {%4,%5,%6,%7}, {%8,%9}, {%0,%1,%2,%3};"
                    : "+f"(acc[ma][na][0]), "+f"(acc[ma][na][1]),
                      "+f"(acc[ma][na][2]), "+f"(acc[ma][na][3])
                    : "r"(c0), "r"(c1), "r"(c2), "r"(c3), "r"(bh[na][0]), "r"(bh[na][1]));
            }
        }
        __syncthreads();
    }
    #pragma unroll
    for (int ma = 0; ma < 2; ma++) {
        int row0 = rowBase + wm * 32 + ma * 16 + gid;
        #pragma unroll
        for (int na = 0; na < 8; na++) {
            int c = wn * 64 + na * 8 + 2 * t;
            int rr = c >> 4, p = c & 15;
            float* base = (p < 8) ? g_qn : g_kn;
            int pp = p & 7;
            if (row0 < NN) {
                float* d0 = base + ((size_t)rr * NN + row0) * HEADS + pp;
                d0[0] = acc[ma][na][0]; d0[1] = acc[ma][na][1];
            }
            if (row0 + 8 < NN) {
                float* d1 = base + ((size_t)rr * NN + row0 + 8) * HEADS + pp;
                d1[0] = acc[ma][na][2]; d1[1] = acc[ma][na][3];
            }
        }
    }
}

// ---------------- 3. xw16 = h16 @ W16  (3-stage cp.async + ldmatrix A) -----
#define ASZ (128 * AROW)   // u32 per stage
#define BSZ (8 * BROW)

__global__ __launch_bounds__(256, 2)
void gemm_f16_kernel() {
    __shared__ __align__(16) uint32_t As[3][ASZ];   // 18432 B
    __shared__ __align__(16) uint32_t Bs[3][BSZ];   // 13056 B
    __shared__ __align__(16) uint32_t Es[64 * 68];  // 17408 B
    int tid = threadIdx.x, wid = tid >> 5, lane = tid & 31;
    int gid = lane >> 2, t = lane & 3;
    int wm = wid >> 1, wn = wid & 1;
    int mtile = blockIdx.x, ntile = blockIdx.y, r = blockIdx.z;
    int rowBase = mtile * 128;
    uint32_t aA = smem_u32(As), bA = smem_u32(Bs);

    float acc[2][8][4];
    #pragma unroll
    for (int i = 0; i < 2; i++)
        #pragma unroll
        for (int j = 0; j < 8; j++)
            #pragma unroll
            for (int q = 0; q < 4; q++) acc[i][j][q] = 0.0f;

    auto fill = [&](int buf, int kc) {
        int k0 = kc * 16;
        int row = tid >> 1, hf = tid & 1;
        cp16(aA + buf * (ASZ * 4) + row * 48 + hf * 16,
             g_h16 + (size_t)(rowBase + row) * F_IN + k0 + hf * 8);
        int kk = tid >> 5, seg = tid & 31;
        cp16(bA + buf * (BSZ * 4) + kk * 544 + seg * 16,
             g_w16p + ((size_t)r * (F_IN / 2) + kc * 8 + kk) * HOUT + ntile * 128 + seg * 4);
    };

    fill(0, 0); CP_COMMIT();
    fill(1, 1); CP_COMMIT();

    uint32_t arow_off = (lane & 15) * 48 + (lane >> 4) * 16;

    for (int kc = 0; kc < 20; kc++) {
        CP_WAIT1();
        __syncthreads();
        if (kc + 2 < 20) fill((kc + 2) % 3, kc + 2);
        CP_COMMIT();
        int buf = kc % 3;
        uint32_t bf[8][2];
        #pragma unroll
        for (int na = 0; na < 8; na++) {
            int n = wn * 64 + na * 8 + gid;
            bf[na][0] = Bs[buf][t * BROW + n];
            bf[na][1] = Bs[buf][(t + 4) * BROW + n];
        }
        #pragma unroll
        for (int ma = 0; ma < 2; ma++) {
            uint32_t a0, a1, a2, a3;
            uint32_t addr = aA + buf * (ASZ * 4) + (wm * 32 + ma * 16) * 48 + arow_off;
            asm volatile("ldmatrix.sync.aligned.m8n8.x4.shared.b16 {%0,%1,%2,%3}, [%4];"
                         : "=r"(a0), "=r"(a1), "=r"(a2), "=r"(a3) : "r"(addr));
            #pragma unroll
            for (int na = 0; na < 8; na++) {
                asm volatile("mma.sync.aligned.m16n8k16.row.col.f32.f16.f16.f32 "
                    "{%0,%1,%2,%3}, {%4,%5,%6,%7}, {%8,%9}, {%0,%1,%2,%3};"
                    : "+f"(acc[ma][na][0]), "+f"(acc[ma][na][1]),
                      "+f"(acc[ma][na][2]), "+f"(acc[ma][na][3])
                    : "r"(a0), "r"(a1), "r"(a2), "r"(a3),
                      "r"(bf[na][0]), "r"(bf[na][1]));
            }
        }
    }

    // staged fp16 epilogue, two halves of 64 rows
    uint32_t* dstb = (uint32_t*)g_xw16 + (size_t)r * NPAD * (HOUT / 2);
    for (int h2 = 0; h2 < 2; h2++) {
        __syncthreads();
        if ((wm >> 1) == h2) {
            int blr = (wm & 1) * 32;
            #pragma unroll
            for (int ma = 0; ma < 2; ma++) {
                int lr = blr + ma * 16 + gid;
                #pragma unroll
                for (int na = 0; na < 8; na++) {
                    int col = wn * 32 + na * 4 + t;
                    Es[lr * 68 + col]       = packh2(acc[ma][na][0], acc[ma][na][1]);
                    Es[(lr + 8) * 68 + col] = packh2(acc[ma][na][2], acc[ma][na][3]);
                }
            }
        }
        __syncthreads();
        #pragma unroll
        for (int j = 0; j < 4; j++) {
            int i = j * 256 + tid;
            int row = i >> 4, c4 = i & 15;
            int grow = rowBase + h2 * 64 + row;
            uint4 v = *(uint4*)&Es[row * 68 + c4 * 4];
            *(uint4*)&dstb[(size_t)grow * (HOUT / 2) + ntile * 64 + c4 * 4] = v;
        }
    }
}

// ---------------- 4. counting sort (parallel scan) -------------------------
__global__ void hist_kernel(const int* __restrict__ ei) {
    int e = blockIdx.x * blockDim.x + threadIdx.x;
    if (e >= EE) return;
    atomicAdd(&g_cnt[ei[EE + e]], 1);
}

__global__ void scan1_kernel() {
    __shared__ int sd[1024];
    int b = blockIdx.x, tid = threadIdx.x, i = b * 1024 + tid;
    int v = (i < NN) ? g_cnt[i] : 0;
    sd[tid] = v;
    __syncthreads();
    for (int o = 1; o < 1024; o <<= 1) {
        int tv = (tid >= o) ? sd[tid - o] : 0;
        __syncthreads();
        sd[tid] += tv;
        __syncthreads();
    }
    if (i < NN) g_off[i + 1] = sd[tid];
    if (tid == 1023) g_bsum[b] = sd[1023];
}

__global__ void scan2_kernel() {
    int tid = threadIdx.x;   // 32
    int v = (tid < 20) ? g_bsum[tid] : 0;
    for (int o = 1; o < 32; o <<= 1) {
        int tv = __shfl_up_sync(0xFFFFFFFF, v, o);
        if (tid >= o) v += tv;
    }
    if (tid < 20) g_bofs[tid] = v - g_bsum[tid];
}

__global__ void scan3_kernel() {
    int b = blockIdx.x, i = b * 1024 + threadIdx.x;
    if (i < NN) g_off[i + 1] += g_bofs[b];
    if (i == 0) g_off[0] = 0;
}

__global__ void copy_woff_kernel() {
    int i = blockIdx.x * blockDim.x + threadIdx.x;
    if (i < NN) g_woff[i] = g_off[i];
}

// ---------------- 5. scatter + edge logits ---------------------------------
__global__ __launch_bounds__(256)
void scatter_kernel(const int* __restrict__ ei, const int* __restrict__ et) {
    int e = blockIdx.x * blockDim.x + threadIdx.x;
    if (e >= EE) return;
    int s = ei[e];
    int d = ei[EE + e];
    int r = et[e];
    int pos = atomicAdd(&g_woff[d], 1);
    g_esort[pos] = s | (r << 16);
    const float* q = g_qn + ((size_t)r * NN + d) * HEADS;
    const float* k = g_kn + ((size_t)r * NN + s) * HEADS;
    float4 q0 = *(const float4*)q,     q1 = *(const float4*)(q + 4);
    float4 k0 = *(const float4*)k,     k1 = *(const float4*)(k + 4);
    float a[8] = { q0.x + k0.x, q0.y + k0.y, q0.z + k0.z, q0.w + k0.w,
                   q1.x + k1.x, q1.y + k1.y, q1.z + k1.z, q1.w + k1.w };
    #pragma unroll
    for (int h = 0; h < 8; h++) a[h] = a[h] > 0.f ? a[h] : 0.2f * a[h];
    float* ap = g_alphas + (size_t)pos * HEADS;
    *(float4*)ap       = make_float4(a[0], a[1], a[2], a[3]);
    *(float4*)(ap + 4) = make_float4(a[4], a[5], a[6], a[7]);
}

// ---------------- 6. fused softmax + aggregate + bias + relu ---------------
__global__ __launch_bounds__(256)
void agg_fused_kernel(const float* __restrict__ bias, float* __restrict__ out) {
    int d = (blockIdx.x * 256 + threadIdx.x) >> 5;
    int lane = threadIdx.x & 31;
    if (d >= NN) return;
    int h = lane >> 2, t = lane & 3;
    int beg = g_off[d], end = g_off[d + 1];

    // single sum pass (logits bounded, max-subtraction unnecessary)
    float ss = 0.f;
    for (int e = beg + t; e < end; e += 4)
        ss += expf(g_alphas[(size_t)e * HEADS + h]);
    ss += __shfl_xor_sync(0xFFFFFFFF, ss, 1);
    ss += __shfl_xor_sync(0xFFFFFFFF, ss, 2);
    float inv = 1.f / (ss + 1e-16f);

    float acc[16];
    #pragma unroll
    for (int j = 0; j < 16; j++) acc[j] = 0.f;

    // weighted gather, 4 edges/iter for deep MLP
    int e = beg;
    for (; e + 3 < end; e += 4) {
        int   p[4];
        float al[4];
        uint4 u0[4], u1[4];
        #pragma unroll
        for (int i = 0; i < 4; i++) {
            p[i]  = g_esort[e + i];
            al[i] = g_alphas[(size_t)(e + i) * HEADS + h];
        }
        #pragma unroll
        for (int i = 0; i < 4; i++) {
            const uint4* rp = (const uint4*)(g_xw16 +
                ((size_t)(p[i] >> 16) * NPAD + (p[i] & 0xFFFF)) * HOUT + lane * 16);
            u0[i] = rp[0];
            u1[i] = rp[1];
        }
        #pragma unroll
        for (int i = 0; i < 4; i++) {
            float w = expf(al[i]) * inv;
            const __half2* x0 = (const __half2*)&u0[i];
            const __half2* x1 = (const __half2*)&u1[i];
            #pragma unroll
            for (int j = 0; j < 4; j++) {
                float2 f = __half22float2(x0[j]);
                acc[2 * j]     += w * f.x;
                acc[2 * j + 1] += w * f.y;
            }
            #pragma unroll
            for (int j = 0; j < 4; j++) {
                float2 f = __half22float2(x1[j]);
                acc[8 + 2 * j]     += w * f.x;
                acc[8 + 2 * j + 1] += w * f.y;
            }
        }
    }
    for (; e < end; e++) {
        int p = g_esort[e];
        float a = g_alphas[(size_t)e * HEADS + h];
        const uint4* rp = (const uint4*)(g_xw16 +
            ((size_t)(p >> 16) * NPAD + (p & 0xFFFF)) * HOUT + lane * 16);
        uint4 u0 = rp[0], u1 = rp[1];
        float w = expf(a) * inv;
        const __half2* x0 = (const __half2*)&u0;
        const __half2* x1 = (const __half2*)&u1;
        #pragma unroll
        for (int j = 0; j < 4; j++) {
            float2 f = __half22float2(x0[j]);
            acc[2 * j]     += w * f.x;
            acc[2 * j + 1] += w * f.y;
        }
        #pragma unroll
        for (int j = 0; j < 4; j++) {
            float2 f = __half22float2(x1[j]);
            acc[8 + 2 * j]     += w * f.x;
            acc[8 + 2 * j + 1] += w * f.y;
        }
    }

    float* orow = out + (size_t)d * HOUT + lane * 16;
    const float4* brow = (const float4*)(bias + lane * 16);
    #pragma unroll
    for (int j4 = 0; j4 < 4; j4++) {
        float4 b = brow[j4];
        float4 v = make_float4(fmaxf(acc[4 * j4 + 0] + b.x, 0.f),
                               fmaxf(acc[4 * j4 + 1] + b.y, 0.f),
                               fmaxf(acc[4 * j4 + 2] + b.z, 0.f),
                               fmaxf(acc[4 * j4 + 3] + b.w, 0.f));
        ((float4*)orow)[j4] = v;
    }
}

// ---------------- launch ---------------------------------------------------
extern "C" void kernel_launch(void* const* d_in, const int* in_sizes, int n_in,
                              void* d_out, int out_size) {
    const float* x        = (const float*)d_in[0];
    const int*   nt       = (const int*)  d_in[1];
    const int*   ei       = (const int*)  d_in[2];
    const int*   et       = (const int*)  d_in[3];
    const float* type_emb = (const float*)d_in[4];
    const float* weight   = (const float*)d_in[5];
    const float* att_q    = (const float*)d_in[6];
    const float* att_k    = (const float*)d_in[7];
    const float* bias     = (const float*)d_in[8];
    float* out = (float*)d_out;

    void* cnt_addr = nullptr;  cudaGetSymbolAddress(&cnt_addr, g_cnt);

    // fork side streams
    cudaEventRecord(g_evF, 0);
    cudaStreamWaitEvent(g_s2, g_evF, 0);
    cudaStreamWaitEvent(g_s3, g_evF, 0);

    // ---- stream 3: W conversion (parallel with build_h) ----
    {
        int total = R * (F_IN / 2) * HOUT;
        convert_w_kernel<<<(total + 255) / 256, 256, 0, g_s3>>>(weight);
    }
    cudaEventRecord(g_evW, g_s3);

    // ---- stream 0: build h, then GEMM ----
    {
        int total = NPAD * (F_IN / 4);
        build_h_kernel<<<(total + 255) / 256, 256>>>(x, nt, type_emb);
    }
    cudaEventRecord(g_evH, 0);
    cudaStreamWaitEvent(0, g_evW, 0);
    {
        dim3 grid(NPAD / 128, HOUT / 128, R);
        gemm_f16_kernel<<<grid, 256>>>();
    }

    // ---- side stream: CSR + qk weights + qkgemm + scatter ----
    cudaMemsetAsync(cnt_addr, 0, NN * sizeof(int), g_s2);
    hist_kernel<<<(EE + 255) / 256, 256, 0, g_s2>>>(ei);
    scan1_kernel<<<20, 1024, 0, g_s2>>>();
    scan2_kernel<<<1, 32, 0, g_s2>>>();
    scan3_kernel<<<20, 1024, 0, g_s2>>>();
    copy_woff_kernel<<<(NN + 255) / 256, 256, 0, g_s2>>>();
    fuse_w_kernel<<<R, 320, 0, g_s2>>>(weight, att_q, att_k);
    {
        int total = (F_IN / 2) * 128;
        split_wqk_kernel<<<(total + 255) / 256, 256, 0, g_s2>>>();
    }
    cudaStreamWaitEvent(g_s2, g_evH, 0);          // qkgemm needs h16
    qkgemm_kernel<<<NPAD / 128, 256, 0, g_s2>>>();
    scatter_kernel<<<(EE + 255) / 256, 256, 0, g_s2>>>(ei, et);
    cudaEventRecord(g_evJ, g_s2);

    // ---- join + final aggregation ----
    cudaStreamWaitEvent(0, g_evJ, 0);
    agg_fused_kernel<<<(NN * 32) / 256, 256>>>(bias, out);
}

// round 13
// speedup vs baseline: 1.1848x; 1.0035x over previous
#include <cuda_runtime.h>
#include <cuda_fp16.h>
#include <math.h>
#include <stdint.h>

// Problem constants
#define NN    20000
#define NPAD  20096      // 157 * 128, padded M for GEMM tiles
#define EE    320000
#define IN_CH 256
#define TYPE_DIM 64
#define F_IN  320
#define R     8
#define HEADS 8
#define HOUT  512

// ---------------- scratch (device globals) --------------------------------
__device__ __half   g_h16[(size_t)NPAD * F_IN];         // fp16 hi part
__device__ __half   g_h16lo[(size_t)NPAD * F_IN];       // fp16 residual
__device__ uint32_t g_w16p[(size_t)R * (F_IN / 2) * HOUT];  // W packed k-pairs half2
__device__ float    g_wqk[(size_t)R * 16 * F_IN];       // fused q/k weights
__device__ uint32_t g_wqk16h[(F_IN / 2) * 128];
__device__ uint32_t g_wqk16l[(F_IN / 2) * 128];
__device__ __half   g_xw16[(size_t)R * NPAD * HOUT];    // xw in fp16 (164 MB)
__device__ float    g_qn[(size_t)R * NN * HEADS];
__device__ float    g_kn[(size_t)R * NN * HEADS];
__device__ float    g_alphas[(size_t)EE * HEADS];       // logits -> softmax weights
__device__ int      g_cnt[NN];
__device__ int      g_off[NN + 1];
__device__ int      g_woff[NN];
__device__ int      g_esort[EE];                        // src | (rel<<16)
__device__ int      g_bsum[20];
__device__ int      g_bofs[20];

// ---------------- side streams + events (created before harness checkpoints)
static cudaStream_t g_s2, g_s3;
static cudaEvent_t  g_evF, g_evH, g_evJ, g_evW;
namespace {
struct StreamInit {
    StreamInit() {
        cudaStreamCreateWithFlags(&g_s2, cudaStreamNonBlocking);
        cudaStreamCreateWithFlags(&g_s3, cudaStreamNonBlocking);
        cudaEventCreateWithFlags(&g_evF, cudaEventDisableTiming);
        cudaEventCreateWithFlags(&g_evH, cudaEventDisableTiming);
        cudaEventCreateWithFlags(&g_evJ, cudaEventDisableTiming);
        cudaEventCreateWithFlags(&g_evW, cudaEventDisableTiming);
    }
};
StreamInit g_streaminit;
}

// ---------------- small helpers -------------------------------------------
__device__ __forceinline__ uint32_t smem_u32(const void* p) {
    uint32_t a;
    asm("{ .reg .u64 t; cvta.to.shared.u64 t, %1; cvt.u32.u64 %0, t; }"
        : "=r"(a) : "l"(p));
    return a;
}
__device__ __forceinline__ void cp16(uint32_t dst, const void* src) {
    asm volatile("cp.async.cg.shared.global [%0], [%1], 16;"
                 :: "r"(dst), "l"(src) : "memory");
}
#define CP_COMMIT() asm volatile("cp.async.commit_group;" ::: "memory")
#define CP_WAIT1()  asm volatile("cp.async.wait_group 1;" ::: "memory")

__device__ __forceinline__ uint32_t packh2(float a, float b) {
    __half2 h = __floats2half2_rn(a, b);
    return *reinterpret_cast<uint32_t*>(&h);
}

// ---------------- 1. build split fp16 h ------------------------------------
__global__ void build_h_kernel(const float* __restrict__ x,
                               const int* __restrict__ nt,
                               const float* __restrict__ type_emb) {
    int idx = blockIdx.x * blockDim.x + threadIdx.x;   // float4 index over NPAD rows
    const int per_row = F_IN / 4;                      // 80
    if (idx >= NPAD * per_row) return;
    int n  = idx / per_row;
    int c4 = idx - n * per_row;
    float4 v = make_float4(0.f, 0.f, 0.f, 0.f);
    if (n < NN) {
        if (c4 < IN_CH / 4) v = *(const float4*)&x[(size_t)n * IN_CH + c4 * 4];
        else {
            int t = nt[n];
            v = *(const float4*)&type_emb[(size_t)t * TYPE_DIM + (c4 - IN_CH / 4) * 4];
        }
    }
    __half2 p0 = __floats2half2_rn(v.x, v.y);
    __half2 p1 = __floats2half2_rn(v.z, v.w);
    ((__half2*)g_h16)[idx * 2 + 0] = p0;
    ((__half2*)g_h16)[idx * 2 + 1] = p1;
    float2 f0 = __half22float2(p0), f1 = __half22float2(p1);
    ((__half2*)g_h16lo)[idx * 2 + 0] = __floats2half2_rn(v.x - f0.x, v.y - f0.y);
    ((__half2*)g_h16lo)[idx * 2 + 1] = __floats2half2_rn(v.z - f1.x, v.w - f1.y);
}

// ---------------- 1b. convert W -> packed half2 k-pairs --------------------
__global__ void convert_w_kernel(const float* __restrict__ W) {
    int idx = blockIdx.x * blockDim.x + threadIdx.x;   // [r][kk][n]
    if (idx >= R * (F_IN / 2) * HOUT) return;
    int r = idx / ((F_IN / 2) * HOUT);
    int rem = idx - r * ((F_IN / 2) * HOUT);
    int kk = rem >> 9;
    int n  = rem & 511;
    float v0 = W[((size_t)r * F_IN + 2 * kk) * HOUT + n];
    float v1 = W[((size_t)r * F_IN + 2 * kk + 1) * HOUT + n];
    g_w16p[idx] = packh2(v0, v1);
}

// ---------------- 1c. fused q/k weights ------------------------------------
__global__ __launch_bounds__(320)
void fuse_w_kernel(const float* __restrict__ W,
                   const float* __restrict__ attq, const float* __restrict__ attk) {
    int r = blockIdx.x;
    __shared__ float att_s[16][HOUT];
    int tid = threadIdx.x;
    for (int i = tid; i < HOUT * HEADS; i += 320) {
        int c = i >> 3, h = i & 7;
        att_s[h][c]     = attq[((size_t)r * HOUT + c) * HEADS + h];
        att_s[8 + h][c] = attk[((size_t)r * HOUT + c) * HEADS + h];
    }
    __syncthreads();
    int f = tid;
    const float* wrow = W + ((size_t)r * F_IN + f) * HOUT;
    float acc[16];
    #pragma unroll
    for (int p = 0; p < 16; p++) acc[p] = 0.0f;
    for (int c = 0; c < HOUT; c += 4) {
        float4 w = *(const float4*)&wrow[c];
        #pragma unroll
        for (int p = 0; p < 16; p++) {
            float4 a = *(const float4*)&att_s[p][c];
            acc[p] += w.x * a.x + w.y * a.y + w.z * a.z + w.w * a.w;
        }
    }
    #pragma unroll
    for (int p = 0; p < 16; p++)
        g_wqk[((size_t)r * 16 + p) * F_IN + f] = acc[p];
}

// ---------------- 1d. split Wqk into hi/lo packed --------------------------
__global__ void split_wqk_kernel() {
    int idx = blockIdx.x * blockDim.x + threadIdx.x;
    if (idx >= (F_IN / 2) * 128) return;
    int kk = idx >> 7;
    int c  = idx & 127;
    float v0 = g_wqk[(size_t)c * F_IN + 2 * kk];
    float v1 = g_wqk[(size_t)c * F_IN + 2 * kk + 1];
    __half h0 = __float2half_rn(v0);
    __half h1 = __float2half_rn(v1);
    g_wqk16h[idx] = packh2(__half2float(h0), __half2float(h1));
    g_wqk16l[idx] = packh2(v0 - __half2float(h0), v1 - __half2float(h1));
}

// ---------------- 2. qn/kn via split-fp16 GEMM (f32 accum, exact logits) ---
#define AROW 12      // u32 per A smem row (48B)
#define BROW 136     // u32 per B smem row (544B)

__global__ __launch_bounds__(256)
void qkgemm_kernel() {
    __shared__ __align__(16) uint32_t Ah[2][128 * AROW];
    __shared__ __align__(16) uint32_t Al[2][128 * AROW];
    __shared__ __align__(16) uint32_t Bh[2][8 * BROW];
    __shared__ __align__(16) uint32_t Bl[2][8 * BROW];
    int tid = threadIdx.x, wid = tid >> 5, lane = tid & 31;
    int gid = lane >> 2, t = lane & 3;
    int wm = wid >> 1, wn = wid & 1;
    int rowBase = blockIdx.x * 128;
    uint32_t ahA = smem_u32(Ah), alA = smem_u32(Al);
    uint32_t bhA = smem_u32(Bh), blA = smem_u32(Bl);

    float acc[2][8][4];
    #pragma unroll
    for (int i = 0; i < 2; i++)
        #pragma unroll
        for (int j = 0; j < 8; j++)
            #pragma unroll
            for (int q = 0; q < 4; q++) acc[i][j][q] = 0.0f;

    auto fill = [&](int buf, int kc) {
        int k0 = kc * 16;
        int row = tid >> 1, hf = tid & 1;
        cp16(ahA + buf * (128 * AROW * 4) + row * 48 + hf * 16,
             g_h16 + (size_t)(rowBase + row) * F_IN + k0 + hf * 8);
        cp16(alA + buf * (128 * AROW * 4) + row * 48 + hf * 16,
             g_h16lo + (size_t)(rowBase + row) * F_IN + k0 + hf * 8);
        int kk = tid >> 5, seg = tid & 31;
        cp16(bhA + buf * (8 * BROW * 4) + kk * 544 + seg * 16,
             g_wqk16h + (kc * 8 + kk) * 128 + seg * 4);
        cp16(blA + buf * (8 * BROW * 4) + kk * 544 + seg * 16,
             g_wqk16l + (kc * 8 + kk) * 128 + seg * 4);
    };

    fill(0, 0); CP_COMMIT();
    for (int kc = 0; kc < 20; kc++) {
        if (kc + 1 < 20) fill((kc + 1) & 1, kc + 1);
        CP_COMMIT();
        CP_WAIT1();
        __syncthreads();
        int buf = kc & 1;
        uint32_t bh[8][2], bl[8][2];
        #pragma unroll
        for (int na = 0; na < 8; na++) {
            int n = wn * 64 + na * 8 + gid;
            bh[na][0] = Bh[buf][t * BROW + n];
            bh[na][1] = Bh[buf][(t + 4) * BROW + n];
            bl[na][0] = Bl[buf][t * BROW + n];
            bl[na][1] = Bl[buf][(t + 4) * BROW + n];
        }
        #pragma unroll
        for (int ma = 0; ma < 2; ma++) {
            int m = wm * 32 + ma * 16 + gid;
            uint32_t a0 = Ah[buf][m * AROW + t],       a1 = Ah[buf][(m + 8) * AROW + t];
            uint32_t a2 = Ah[buf][m * AROW + t + 4],   a3 = Ah[buf][(m + 8) * AROW + t + 4];
            uint32_t c0 = Al[buf][m * AROW + t],       c1 = Al[buf][(m + 8) * AROW + t];
            uint32_t c2 = Al[buf][m * AROW + t + 4],   c3 = Al[buf][(m + 8) * AROW + t + 4];
            #pragma unroll
            for (int na = 0; na < 8; na++) {
                asm volatile("mma.sync.aligned.m16n8k16.row.col.f32.f16.f16.f32 "
                    "{%0,%1,%2,%3}, {%4,%5,%6,%7}, {%8,%9}, {%0,%1,%2,%3};"
                    : "+f"(acc[ma][na][0]), "+f"(acc[ma][na][1]),
                      "+f"(acc[ma][na][2]), "+f"(acc[ma][na][3])
                    : "r"(a0), "r"(a1), "r"(a2), "r"(a3), "r"(bh[na][0]), "r"(bh[na][1]));
                asm volatile("mma.sync.aligned.m16n8k16.row.col.f32.f16.f16.f32 "
                    "{%0,%1,%2,%3}, {%4,%5,%6,%7}, {%8,%9}, {%0,%1,%2,%3};"
                    : "+f"(acc[ma][na][0]), "+f"(acc[ma][na][1]),
                      "+f"(acc[ma][na][2]), "+f"(acc[ma][na][3])
                    : "r"(a0), "r"(a1), "r"(a2), "r"(a3), "r"(bl[na][0]), "r"(bl[na][1]));
                asm volatile("mma.sync.aligned.m16n8k16.row.col.f32.f16.f16.f32 "
                    "{%0,%1,%2,%3}, {%4,%5,%6,%7}, {%8,%9}, {%0,%1,%2,%3};"
                    : "+f"(acc[ma][na][0]), "+f"(acc[ma][na][1]),
                      "+f"(acc[ma][na][2]), "+f"(acc[ma][na][3])
                    : "r"(c0), "r"(c1), "r"(c2), "r"(c3), "r"(bh[na][0]), "r"(bh[na][1]));
            }
        }
        __syncthreads();
    }
    #pragma unroll
    for (int ma = 0; ma < 2; ma++) {
        int row0 = rowBase + wm * 32 + ma * 16 + gid;
        #pragma unroll
        for (int na = 0; na < 8; na++) {
            int c = wn * 64 + na * 8 + 2 * t;
            int rr = c >> 4, p = c & 15;
            float* base = (p < 8) ? g_qn : g_kn;
            int pp = p & 7;
            if (row0 < NN) {
                float* d0 = base + ((size_t)rr * NN + row0) * HEADS + pp;
                d0[0] = acc[ma][na][0]; d0[1] = acc[ma][na][1];
            }
            if (row0 + 8 < NN) {
                float* d1 = base + ((size_t)rr * NN + row0 + 8) * HEADS + pp;
                d1[0] = acc[ma][na][2]; d1[1] = acc[ma][na][3];
            }
        }
    }
}

// ---------------- 3. xw16 = h16 @ W16  (3-stage cp.async + ldmatrix A) -----
#define ASZ (128 * AROW)   // u32 per stage
#define BSZ (8 * BROW)

__global__ __launch_bounds__(256, 2)
void gemm_f16_kernel() {
    __shared__ __align__(16) uint32_t As[3][ASZ];   // 18432 B
    __shared__ __align__(16) uint32_t Bs[3][BSZ];   // 13056 B
    __shared__ __align__(16) uint32_t Es[64 * 68];  // 17408 B
    int tid = threadIdx.x, wid = tid >> 5, lane = tid & 31;
    int gid = lane >> 2, t = lane & 3;
    int wm = wid >> 1, wn = wid & 1;
    int mtile = blockIdx.x, ntile = blockIdx.y, r = blockIdx.z;
    int rowBase = mtile * 128;
    uint32_t aA = smem_u32(As), bA = smem_u32(Bs);

    float acc[2][8][4];
    #pragma unroll
    for (int i = 0; i < 2; i++)
        #pragma unroll
        for (int j = 0; j < 8; j++)
            #pragma unroll
            for (int q = 0; q < 4; q++) acc[i][j][q] = 0.0f;

    auto fill = [&](int buf, int kc) {
        int k0 = kc * 16;
        int row = tid >> 1, hf = tid & 1;
        cp16(aA + buf * (ASZ * 4) + row * 48 + hf * 16,
             g_h16 + (size_t)(rowBase + row) * F_IN + k0 + hf * 8);
        int kk = tid >> 5, seg = tid & 31;
        cp16(bA + buf * (BSZ * 4) + kk * 544 + seg * 16,
             g_w16p + ((size_t)r * (F_IN / 2) + kc * 8 + kk) * HOUT + ntile * 128 + seg * 4);
    };

    fill(0, 0); CP_COMMIT();
    fill(1, 1); CP_COMMIT();

    uint32_t arow_off = (lane & 15) * 48 + (lane >> 4) * 16;

    for (int kc = 0; kc < 20; kc++) {
        CP_WAIT1();
        __syncthreads();
        if (kc + 2 < 20) fill((kc + 2) % 3, kc + 2);
        CP_COMMIT();
        int buf = kc % 3;
        uint32_t bf[8][2];
        #pragma unroll
        for (int na = 0; na < 8; na++) {
            int n = wn * 64 + na * 8 + gid;
            bf[na][0] = Bs[buf][t * BROW + n];
            bf[na][1] = Bs[buf][(t + 4) * BROW + n];
        }
        #pragma unroll
        for (int ma = 0; ma < 2; ma++) {
            uint32_t a0, a1, a2, a3;
            uint32_t addr = aA + buf * (ASZ * 4) + (wm * 32 + ma * 16) * 48 + arow_off;
            asm volatile("ldmatrix.sync.aligned.m8n8.x4.shared.b16 {%0,%1,%2,%3}, [%4];"
                         : "=r"(a0), "=r"(a1), "=r"(a2), "=r"(a3) : "r"(addr));
            #pragma unroll
            for (int na = 0; na < 8; na++) {
                asm volatile("mma.sync.aligned.m16n8k16.row.col.f32.f16.f16.f32 "
                    "{%0,%1,%2,%3}, {%4,%5,%6,%7}, {%8,%9}, {%0,%1,%2,%3};"
                    : "+f"(acc[ma][na][0]), "+f"(acc[ma][na][1]),
                      "+f"(acc[ma][na][2]), "+f"(acc[ma][na][3])
                    : "r"(a0), "r"(a1), "r"(a2), "r"(a3),
                      "r"(bf[na][0]), "r"(bf[na][1]));
            }
        }
    }

    // staged fp16 epilogue, two halves of 64 rows
    uint32_t* dstb = (uint32_t*)g_xw16 + (size_t)r * NPAD * (HOUT / 2);
    for (int h2 = 0; h2 < 2; h2++) {
        __syncthreads();
        if ((wm >> 1) == h2) {
            int blr = (wm & 1) * 32;
            #pragma unroll
            for (int ma = 0; ma < 2; ma++) {
                int lr = blr + ma * 16 + gid;
                #pragma unroll
                for (int na = 0; na < 8; na++) {
                    int col = wn * 32 + na * 4 + t;
                    Es[lr * 68 + col]       = packh2(acc[ma][na][0], acc[ma][na][1]);
                    Es[(lr + 8) * 68 + col] = packh2(acc[ma][na][2], acc[ma][na][3]);
                }
            }
        }
        __syncthreads();
        #pragma unroll
        for (int j = 0; j < 4; j++) {
            int i = j * 256 + tid;
            int row = i >> 4, c4 = i & 15;
            int grow = rowBase + h2 * 64 + row;
            uint4 v = *(uint4*)&Es[row * 68 + c4 * 4];
            *(uint4*)&dstb[(size_t)grow * (HOUT / 2) + ntile * 64 + c4 * 4] = v;
        }
    }
}

// ---------------- 4. counting sort (parallel scan) -------------------------
__global__ void hist_kernel(const int* __restrict__ ei) {
    int e = blockIdx.x * blockDim.x + threadIdx.x;
    if (e >= EE) return;
    atomicAdd(&g_cnt[ei[EE + e]], 1);
}

__global__ void scan1_kernel() {
    __shared__ int sd[1024];
    int b = blockIdx.x, tid = threadIdx.x, i = b * 1024 + tid;
    int v = (i < NN) ? g_cnt[i] : 0;
    sd[tid] = v;
    __syncthreads();
    for (int o = 1; o < 1024; o <<= 1) {
        int tv = (tid >= o) ? sd[tid - o] : 0;
        __syncthreads();
        sd[tid] += tv;
        __syncthreads();
    }
    if (i < NN) g_off[i + 1] = sd[tid];
    if (tid == 1023) g_bsum[b] = sd[1023];
}

__global__ void scan2_kernel() {
    int tid = threadIdx.x;   // 32
    int v = (tid < 20) ? g_bsum[tid] : 0;
    for (int o = 1; o < 32; o <<= 1) {
        int tv = __shfl_up_sync(0xFFFFFFFF, v, o);
        if (tid >= o) v += tv;
    }
    if (tid < 20) g_bofs[tid] = v - g_bsum[tid];
}

__global__ void scan3_kernel() {
    int b = blockIdx.x, i = b * 1024 + threadIdx.x;
    if (i < NN) g_off[i + 1] += g_bofs[b];
    if (i == 0) g_off[0] = 0;
}

__global__ void copy_woff_kernel() {
    int i = blockIdx.x * blockDim.x + threadIdx.x;
    if (i < NN) g_woff[i] = g_off[i];
}

// ---------------- 5. scatter + edge logits ---------------------------------
__global__ __launch_bounds__(256)
void scatter_kernel(const int* __restrict__ ei, const int* __restrict__ et) {
    int e = blockIdx.x * blockDim.x + threadIdx.x;
    if (e >= EE) return;
    int s = ei[e];
    int d = ei[EE + e];
    int r = et[e];
    int pos = atomicAdd(&g_woff[d], 1);
    g_esort[pos] = s | (r << 16);
    const float* q = g_qn + ((size_t)r * NN + d) * HEADS;
    const float* k = g_kn + ((size_t)r * NN + s) * HEADS;
    float4 q0 = *(const float4*)q,     q1 = *(const float4*)(q + 4);
    float4 k0 = *(const float4*)k,     k1 = *(const float4*)(k + 4);
    float a[8] = { q0.x + k0.x, q0.y + k0.y, q0.z + k0.z, q0.w + k0.w,
                   q1.x + k1.x, q1.y + k1.y, q1.z + k1.z, q1.w + k1.w };
    #pragma unroll
    for (int h = 0; h < 8; h++) a[h] = a[h] > 0.f ? a[h] : 0.2f * a[h];
    float* ap = g_alphas + (size_t)pos * HEADS;
    *(float4*)ap       = make_float4(a[0], a[1], a[2], a[3]);
    *(float4*)(ap + 4) = make_float4(a[4], a[5], a[6], a[7]);
}

// ---------------- 5b. softmax weights in place (overlapped with GEMM) ------
__global__ __launch_bounds__(256)
void weights_kernel() {
    int d = (blockIdx.x * 256 + threadIdx.x) >> 5;
    int lane = threadIdx.x & 31;
    if (d >= NN) return;
    int h = lane >> 2, t = lane & 3;
    int beg = g_off[d], end = g_off[d + 1];

    float ss = 0.f;
    for (int e = beg + t; e < end; e += 4)
        ss += expf(g_alphas[(size_t)e * HEADS + h]);
    ss += __shfl_xor_sync(0xFFFFFFFF, ss, 1);
    ss += __shfl_xor_sync(0xFFFFFFFF, ss, 2);
    float inv = 1.f / (ss + 1e-16f);

    for (int e = beg + t; e < end; e += 4) {
        float a = g_alphas[(size_t)e * HEADS + h];
        g_alphas[(size_t)e * HEADS + h] = expf(a) * inv;
    }
}

// ---------------- 6. aggregate (precomputed weights) + bias + relu ---------
__global__ __launch_bounds__(256)
void agg_fused_kernel(const float* __restrict__ bias, float* __restrict__ out) {
    int d = (blockIdx.x * 256 + threadIdx.x) >> 5;
    int lane = threadIdx.x & 31;
    if (d >= NN) return;
    int h = lane >> 2;
    int beg = g_off[d], end = g_off[d + 1];

    float acc[16];
    #pragma unroll
    for (int j = 0; j < 16; j++) acc[j] = 0.f;

    // weighted gather, 4 edges/iter for deep MLP
    int e = beg;
    for (; e + 3 < end; e += 4) {
        int   p[4];
        float w[4];
        uint4 u0[4], u1[4];
        #pragma unroll
        for (int i = 0; i < 4; i++) {
            p[i] = g_esort[e + i];
            w[i] = g_alphas[(size_t)(e + i) * HEADS + h];
        }
        #pragma unroll
        for (int i = 0; i < 4; i++) {
            const uint4* rp = (const uint4*)(g_xw16 +
                ((size_t)(p[i] >> 16) * NPAD + (p[i] & 0xFFFF)) * HOUT + lane * 16);
            u0[i] = rp[0];
            u1[i] = rp[1];
        }
        #pragma unroll
        for (int i = 0; i < 4; i++) {
            const __half2* x0 = (const __half2*)&u0[i];
            const __half2* x1 = (const __half2*)&u1[i];
            #pragma unroll
            for (int j = 0; j < 4; j++) {
                float2 f = __half22float2(x0[j]);
                acc[2 * j]     += w[i] * f.x;
                acc[2 * j + 1] += w[i] * f.y;
            }
            #pragma unroll
            for (int j = 0; j < 4; j++) {
                float2 f = __half22float2(x1[j]);
                acc[8 + 2 * j]     += w[i] * f.x;
                acc[8 + 2 * j + 1] += w[i] * f.y;
            }
        }
    }
    for (; e < end; e++) {
        int p = g_esort[e];
        float w = g_alphas[(size_t)e * HEADS + h];
        const uint4* rp = (const uint4*)(g_xw16 +
            ((size_t)(p >> 16) * NPAD + (p & 0xFFFF)) * HOUT + lane * 16);
        uint4 u0 = rp[0], u1 = rp[1];
        const __half2* x0 = (const __half2*)&u0;
        const __half2* x1 = (const __half2*)&u1;
        #pragma unroll
        for (int j = 0; j < 4; j++) {
            float2 f = __half22float2(x0[j]);
            acc[2 * j]     += w * f.x;
            acc[2 * j + 1] += w * f.y;
        }
        #pragma unroll
        for (int j = 0; j < 4; j++) {
            float2 f = __half22float2(x1[j]);
            acc[8 + 2 * j]     += w * f.x;
            acc[8 + 2 * j + 1] += w * f.y;
        }
    }

    float* orow = out + (size_t)d * HOUT + lane * 16;
    const float4* brow = (const float4*)(bias + lane * 16);
    #pragma unroll
    for (int j4 = 0; j4 < 4; j4++) {
        float4 b = brow[j4];
        float4 v = make_float4(fmaxf(acc[4 * j4 + 0] + b.x, 0.f),
                               fmaxf(acc[4 * j4 + 1] + b.y, 0.f),
                               fmaxf(acc[4 * j4 + 2] + b.z, 0.f),
                               fmaxf(acc[4 * j4 + 3] + b.w, 0.f));
        ((float4*)orow)[j4] = v;
    }
}

// ---------------- launch ---------------------------------------------------
extern "C" void kernel_launch(void* const* d_in, const int* in_sizes, int n_in,
                              void* d_out, int out_size) {
    const float* x        = (const float*)d_in[0];
    const int*   nt       = (const int*)  d_in[1];
    const int*   ei       = (const int*)  d_in[2];
    const int*   et       = (const int*)  d_in[3];
    const float* type_emb = (const float*)d_in[4];
    const float* weight   = (const float*)d_in[5];
    const float* att_q    = (const float*)d_in[6];
    const float* att_k    = (const float*)d_in[7];
    const float* bias     = (const float*)d_in[8];
    float* out = (float*)d_out;

    void* cnt_addr = nullptr;  cudaGetSymbolAddress(&cnt_addr, g_cnt);

    // fork side streams
    cudaEventRecord(g_evF, 0);
    cudaStreamWaitEvent(g_s2, g_evF, 0);
    cudaStreamWaitEvent(g_s3, g_evF, 0);

    // ---- stream 3: W conversion (parallel with build_h) ----
    {
        int total = R * (F_IN / 2) * HOUT;
        convert_w_kernel<<<(total + 255) / 256, 256, 0, g_s3>>>(weight);
    }
    cudaEventRecord(g_evW, g_s3);

    // ---- stream 0: build h, then GEMM ----
    {
        int total = NPAD * (F_IN / 4);
        build_h_kernel<<<(total + 255) / 256, 256>>>(x, nt, type_emb);
    }
    cudaEventRecord(g_evH, 0);
    cudaStreamWaitEvent(0, g_evW, 0);
    {
        dim3 grid(NPAD / 128, HOUT / 128, R);
        gemm_f16_kernel<<<grid, 256>>>();
    }

    // ---- side stream: CSR + qk weights + qkgemm + scatter + softmax ----
    cudaMemsetAsync(cnt_addr, 0, NN * sizeof(int), g_s2);
    hist_kernel<<<(EE + 255) / 256, 256, 0, g_s2>>>(ei);
    scan1_kernel<<<20, 1024, 0, g_s2>>>();
    scan2_kernel<<<1, 32, 0, g_s2>>>();
    scan3_kernel<<<20, 1024, 0, g_s2>>>();
    copy_woff_kernel<<<(NN + 255) / 256, 256, 0, g_s2>>>();
    fuse_w_kernel<<<R, 320, 0, g_s2>>>(weight, att_q, att_k);
    {
        int total = (F_IN / 2) * 128;
        split_wqk_kernel<<<(total + 255) / 256, 256, 0, g_s2>>>();
    }
    cudaStreamWaitEvent(g_s2, g_evH, 0);          // qkgemm needs h16
    qkgemm_kernel<<<NPAD / 128, 256, 0, g_s2>>>();
    scatter_kernel<<<(EE + 255) / 256, 256, 0, g_s2>>>(ei, et);
    weights_kernel<<<(NN * 32) / 256, 256, 0, g_s2>>>();
    cudaEventRecord(g_evJ, g_s2);

    // ---- join + final aggregation (pure gather) ----
    cudaStreamWaitEvent(0, g_evJ, 0);
    agg_fused_kernel<<<(NN * 32) / 256, 256>>>(bias, out);
}